// round 5
// baseline (speedup 1.0000x reference)
#include <cuda_runtime.h>

// out = kipf - lbda[row] * input
// input, kipf: [100000, 256] fp32; lbda: [100000] fp32
// Persistent grid-stride: exactly one full occupancy wave (148 SMs x 8 CTAs of
// 256 threads), each thread loops ~21 float4s. Evict-first loads on the two
// dead streams; lbda stays cached (400KB, reused, broadcast).

#define NUM_SMS      148
#define CTAS_PER_SM  8
#define THREADS      256

__global__ __launch_bounds__(THREADS) void damping_kernel(
    const float4* __restrict__ input4,
    const float4* __restrict__ kipf4,
    const float*  __restrict__ lbda,
    float4* __restrict__ out4,
    int n4)
{
    const int stride = gridDim.x * THREADS;
    for (int i = blockIdx.x * THREADS + threadIdx.x; i < n4; i += stride) {
        int row = i >> 6;               // 64 float4 per 256-float row
        float l = __ldg(&lbda[row]);

        float4 a = __ldcs(input4 + i);  // dead after use
        float4 k = __ldcs(kipf4  + i);  // dead after use

        float4 r;
        r.x = fmaf(-l, a.x, k.x);
        r.y = fmaf(-l, a.y, k.y);
        r.z = fmaf(-l, a.z, k.z);
        r.w = fmaf(-l, a.w, k.w);

        out4[i] = r;
    }
}

extern "C" void kernel_launch(void* const* d_in, const int* in_sizes, int n_in,
                              void* d_out, int out_size) {
    const float4* input4 = (const float4*)d_in[0];   // input_term
    const float4* kipf4  = (const float4*)d_in[1];   // kipf_term
    const float*  lbda   = (const float*)d_in[2];    // lbda
    // d_in[3] = spar (unused, always 1)

    int n4 = out_size / 4;               // 6,400,000 float4
    int blocks = NUM_SMS * CTAS_PER_SM;  // 1184 = one full wave

    damping_kernel<<<blocks, THREADS>>>(input4, kipf4, lbda, (float4*)d_out, n4);
}

// round 8
// speedup vs baseline: 1.0921x; 1.0921x over previous
#include <cuda_runtime.h>

// out = kipf - lbda[row] * input
// input, kipf: [100000, 256] fp32; lbda: [100000] fp32
// Final config (R1): 1 float4/thread, 256-thread blocks, 25000 blocks.
// Memory-roofline kernel at ~95% of the sm_103a LTS path-independent cap;
// structural variants (unroll, ldcs, 512-thr, persistent) all within noise.

__global__ __launch_bounds__(256) void damping_kernel(
    const float4* __restrict__ input4,
    const float4* __restrict__ kipf4,
    const float*  __restrict__ lbda,
    float4* __restrict__ out4,
    int n4)  // total float4 count
{
    int i = blockIdx.x * blockDim.x + threadIdx.x;
    if (i >= n4) return;

    int row = i >> 6;               // 64 float4 per 256-float row
    float l = __ldg(&lbda[row]);    // broadcast across 64 consecutive threads

    float4 a = input4[i];
    float4 k = kipf4[i];

    float4 r;
    r.x = fmaf(-l, a.x, k.x);
    r.y = fmaf(-l, a.y, k.y);
    r.z = fmaf(-l, a.z, k.z);
    r.w = fmaf(-l, a.w, k.w);

    out4[i] = r;
}

extern "C" void kernel_launch(void* const* d_in, const int* in_sizes, int n_in,
                              void* d_out, int out_size) {
    const float4* input4 = (const float4*)d_in[0];   // input_term
    const float4* kipf4  = (const float4*)d_in[1];   // kipf_term
    const float*  lbda   = (const float*)d_in[2];    // lbda
    // d_in[3] = spar (unused scalar, always 1)

    int n  = out_size;        // 25,600,000
    int n4 = n / 4;           // 6,400,000

    int threads = 256;
    int blocks  = (n4 + threads - 1) / threads;  // 25000
    damping_kernel<<<blocks, threads>>>(input4, kipf4, lbda, (float4*)d_out, n4);
}